// round 15
// baseline (speedup 1.0000x reference)
#include <cuda_runtime.h>

// AdaptiveFeaturePooling: 4-level ROIAlign (out=14, sr=2) + max over levels.
// SINGLE kernel, grid = R (all blocks fit in wave 1, homogeneous):
//   each block: bilinear tables + mask + release-published worklist entries;
//   signal g_bdone; skip-fill own ROI slice (zero invalid cells only); then
//   all 8 warps join a chip-wide pop pool and drain the worklist (~1 entry
//   per warp: 8x32-channel rounds, 16 indep. LDGs per thread per round,
//   shfl butterfly over 4-lane x-tap groups).
// Valid cells are written only by consumers, invalid only by the fill ->
// disjoint, no ordering needed between them. Publish precedes fill, so
// entry polling always makes progress. Counters/worklist self-reset.

#define OUTSZ  14
#define CELLS  196
#define CH     256
#define GSAMP  28           // OUTSZ*2
#define MAXROI 512
#define NF4    ((CH * CELLS) / 4)   // 12544 float4 per ROI slice
#define NGRP   (NF4 / CH)           // 49 float4 groups per channel

__device__ float4 g_tab[MAXROI][4][2][GSAMP];  // {w0,w1,lo,hi}
__device__ unsigned g_work[MAXROI * CELLS];    // (r<<12)|(cell<<4)|m, 0=unpublished
__device__ int g_count;
__device__ int g_bdone;
__device__ int g_pop;
__device__ int g_ticket;

__device__ __forceinline__ int ldacq_s32(const int* p)
{
    int v; asm volatile("ld.acquire.gpu.s32 %0, [%1];" : "=r"(v) : "l"(p)); return v;
}
__device__ __forceinline__ unsigned ldacq_u32(const unsigned* p)
{
    unsigned v; asm volatile("ld.acquire.gpu.u32 %0, [%1];" : "=r"(v) : "l"(p)); return v;
}
__device__ __forceinline__ void strel_u32(unsigned* p, unsigned v)
{
    asm volatile("st.release.gpu.u32 [%0], %1;" :: "l"(p), "r"(v) : "memory");
}

// Warp-level pop-and-compute; returns when the worklist is drained.
__device__ __forceinline__ void consume_warp(
    const float* __restrict__ f0, const float* __restrict__ f1,
    const float* __restrict__ f2, const float* __restrict__ f3,
    float* __restrict__ out, int R)
{
    const int lane = threadIdx.x & 31;
    const int xi   = lane & 3;          // x-tap index
    const int c8   = lane >> 2;         // channel sub-index 0..7
    const float* fl[4] = { f0, f1, f2, f3 };

    for (;;) {
        int t = 0;
        if (lane == 0) t = atomicAdd(&g_pop, 1);
        t = __shfl_sync(0xFFFFFFFFu, t, 0);

        // Wait until ticket t is covered by the (monotone) published count,
        // or the list is finalized and drained.
        unsigned w = 0;
        if (lane == 0) {
            for (;;) {
                int c = ldacq_s32(&g_count);
                if (t < c) break;
                if (ldacq_s32(&g_bdone) == R) { c = ldacq_s32(&g_count); if (t >= c) { w = 0xFFFFFFFFu; } break; }
                __nanosleep(128);
            }
            if (w != 0xFFFFFFFFu) {
                // Entry t WILL be published (count already covers it).
                w = ldacq_u32(&g_work[t]);
                while (w == 0u) { __nanosleep(64); w = ldacq_u32(&g_work[t]); }
            }
        }
        w = __shfl_sync(0xFFFFFFFFu, w, 0);
        if (w == 0xFFFFFFFFu) break;     // drained

        int r    = (int)(w >> 12);
        int cell = (int)((w >> 4) & 0xFF);
        unsigned m = w & 0xF;
        int py = cell / OUTSZ;
        int px = cell - py * OUTSZ;
        int sy = 2 * py, sx = 2 * px;

        float* obase = out + (size_t)r * (CH * CELLS) + cell;

        #pragma unroll 2
        for (int b = 0; b < 8; ++b) {    // 8 rounds x 32 channels
            const int cb = c8 + 32 * b;  // channels cb, cb+8, cb+16, cb+24
            float best[4] = {0.f, 0.f, 0.f, 0.f};

            #pragma unroll
            for (int l = 0; l < 4; ++l) {
                if (m & (1u << l)) {
                    const int W = 224 >> l;
                    float4 ty0 = g_tab[r][l][0][sy];
                    float4 ty1 = g_tab[r][l][0][sy + 1];
                    float4 tx0 = g_tab[r][l][1][sx];
                    float4 tx1 = g_tab[r][l][1][sx + 1];

                    float wx; int x;
                    if (xi == 0)      { wx = tx0.x; x = __float_as_int(tx0.z); }
                    else if (xi == 1) { wx = tx0.y; x = __float_as_int(tx0.w); }
                    else if (xi == 2) { wx = tx1.x; x = __float_as_int(tx1.z); }
                    else              { wx = tx1.y; x = __float_as_int(tx1.w); }

                    int y0 = __float_as_int(ty0.z) * W;
                    int y1 = __float_as_int(ty0.w) * W;
                    int y2 = __float_as_int(ty1.z) * W;
                    int y3 = __float_as_int(ty1.w) * W;

                    float v[4][4];
                    #pragma unroll
                    for (int u = 0; u < 4; ++u) {
                        const float* fc = fl[l] + (size_t)(cb + 8 * u) * (W * W);
                        v[u][0] = fc[y0 + x];
                        v[u][1] = fc[y1 + x];
                        v[u][2] = fc[y2 + x];
                        v[u][3] = fc[y3 + x];
                    }
                    #pragma unroll
                    for (int u = 0; u < 4; ++u) {
                        float s = wx * (ty0.x * v[u][0] + ty0.y * v[u][1]
                                      + ty1.x * v[u][2] + ty1.y * v[u][3]);
                        s += __shfl_xor_sync(0xFFFFFFFFu, s, 1);
                        s += __shfl_xor_sync(0xFFFFFFFFu, s, 2);
                        best[u] = fmaxf(best[u], s * 0.25f);
                    }
                }
            }
            if (xi == 0) {
                #pragma unroll
                for (int u = 0; u < 4; ++u)
                    obase[(size_t)(cb + 8 * u) * CELLS] = best[u];
            }
        }

        if (lane == 0) g_work[t] = 0u;   // re-zero for next graph replay
    }
}

__global__ __launch_bounds__(256, 4)
void afp_fused(const float* __restrict__ f0, const float* __restrict__ f1,
               const float* __restrict__ f2, const float* __restrict__ f3,
               const float* __restrict__ rois, int R, float* __restrict__ out)
{
    __shared__ float s_w0[4][2][GSAMP];
    __shared__ float s_w1[4][2][GSAMP];
    __shared__ unsigned char s_m[CELLS];
    __shared__ unsigned char s_anyv[NGRP];
    __shared__ int s_skip;

    const int tid = threadIdx.x;
    const int r   = blockIdx.x;

    // Phase A: bilinear prep (reference fp32 op order, exactly).
    if (tid < 4 * 2 * GSAMP) {
        int l   = tid / (2 * GSAMP);
        int rem = tid - l * (2 * GSAMP);
        int a   = rem / GSAMP;           // 0=y, 1=x
        int j   = rem - a * GSAMP;

        float p1 = rois[r * 4 + (a == 0 ? 1 : 0)];
        float p2 = rois[r * 4 + (a == 0 ? 3 : 2)];
        #pragma unroll
        for (int i = 3; i >= 0; --i) {
            if (i >= l) {
                float s = (float)(28 << i);
                p1 = __fmul_rn(p1, s);
                p2 = __fmul_rn(p2, s);
            }
        }
        float len  = fmaxf(__fadd_rn(p2, -p1), 1.0f);
        float t    = __fdiv_rn(len, 14.0f);
        float step = ((float)j + 0.5f) * 0.5f;
        float c    = __fadd_rn(p1, __fmul_rn(step, t));

        int L = 224 >> l;
        bool valid = (c >= -1.0f) && (c <= (float)L);
        c = fminf(fmaxf(c, 0.0f), (float)(L - 1));
        float lo   = floorf(c);
        float frac = __fadd_rn(c, -lo);
        int loi = (int)lo;
        int hii = loi + 1;
        if (loi >= L - 1) { loi = L - 1; hii = L - 1; frac = 0.0f; }
        float v  = valid ? 1.0f : 0.0f;
        float w0 = (1.0f - frac) * v;
        float w1 = frac * v;
        s_w0[l][a][j] = w0;
        s_w1[l][a][j] = w1;
        g_tab[r][l][a][j] = make_float4(w0, w1, __int_as_float(loi), __int_as_float(hii));
    }
    __syncthreads();

    // Phase B: mask + release-publish worklist entries.
    if (tid < CELLS) {
        int py = tid / OUTSZ;
        int px = tid - py * OUTSZ;
        unsigned m = 0;
        #pragma unroll
        for (int l = 0; l < 4; ++l) {
            float wy = s_w0[l][0][2*py]   + s_w1[l][0][2*py]
                     + s_w0[l][0][2*py+1] + s_w1[l][0][2*py+1];
            float wx = s_w0[l][1][2*px]   + s_w1[l][1][2*px]
                     + s_w0[l][1][2*px+1] + s_w1[l][1][2*px+1];
            if (wy > 0.0f && wx > 0.0f) m |= (1u << l);
        }
        s_m[tid] = (unsigned char)m;
        if (m) {
            int pos = atomicAdd(&g_count, 1);
            strel_u32(&g_work[pos], ((unsigned)r << 12) | ((unsigned)tid << 4) | m);
        }
    }
    __syncthreads();

    // Finalize-publish signal for drain detection.
    if (tid == 0) {
        __threadfence();
        atomicAdd(&g_bdone, 1);
    }

    if (tid < NGRP) {
        int k = tid * 4;
        s_anyv[tid] = (unsigned char)(s_m[k] | s_m[k+1] | s_m[k+2] | s_m[k+3]);
    }
    __syncthreads();

    // Skip-fill: zero all invalid cells of this ROI's slice (valid cells are
    // written exclusively by consumers -> disjoint).
    {
        float* obase = out + (size_t)r * (CH * CELLS);
        float4* o4 = reinterpret_cast<float4*>(obase);
        const float4 z4 = make_float4(0.f, 0.f, 0.f, 0.f);
        int k = tid % NGRP;
        #pragma unroll 4
        for (int i = tid; i < NF4; i += 256) {
            if (!s_anyv[k]) {
                o4[i] = z4;
            } else {
                int cell0 = k * 4;
                float* p = obase + i * 4;
                #pragma unroll
                for (int q = 0; q < 4; ++q)
                    if (!s_m[cell0 + q]) p[q] = 0.0f;
            }
            k += 256 % NGRP;             // 11
            if (k >= NGRP) k -= NGRP;
        }
    }

    // Drained gate: late blocks skip the pop pool entirely (saves atomics).
    if (tid == 0) {
        s_skip = (ldacq_s32(&g_bdone) == R &&
                  *(volatile int*)&g_pop >= *(volatile int*)&g_count) ? 1 : 0;
    }
    __syncthreads();

    if (!s_skip)
        consume_warp(f0, f1, f2, f3, out, R);

    // Self-reset: last block zeroes counters for the next graph replay.
    __syncthreads();
    if (tid == 0) {
        int t = atomicAdd(&g_ticket, 1);
        if (t == R - 1) {
            g_count  = 0;
            g_bdone  = 0;
            g_pop    = 0;
            g_ticket = 0;
        }
    }
}

extern "C" void kernel_launch(void* const* d_in, const int* in_sizes, int n_in,
                              void* d_out, int out_size)
{
    const float* f0   = (const float*)d_in[0];
    const float* f1   = (const float*)d_in[1];
    const float* f2   = (const float*)d_in[2];
    const float* f3   = (const float*)d_in[3];
    const float* rois = (const float*)d_in[4];
    int R = in_sizes[4] / 4;

    afp_fused<<<R, 256>>>(f0, f1, f2, f3, rois, R, (float*)d_out);
}

// round 16
// speedup vs baseline: 1.0645x; 1.0645x over previous
#include <cuda_runtime.h>

// AdaptiveFeaturePooling: 4-level ROIAlign (out=14, sr=2) + max over levels.
// 2 graph nodes (components individually measured in earlier rounds):
//   1) fill+build: 2048 blocks; all grid-stride a coalesced float4 zero-fill
//      of the output; blocks < R first build bilinear tables + compacted
//      worklist (hidden under the fill).          [~14 us, write-bound]
//   2) scatter: 256 blocks (single wave), one worklist entry per WARP;
//      8x32-channel rounds, 16 independent LDGs per thread per round
//      (unroll 2 -> 32 in flight), shfl butterfly over 4-lane x-tap groups.
//      Counter self-resets via exit ticket.        [~3-4 us]

#define OUTSZ  14
#define CELLS  196
#define CH     256
#define GSAMP  28           // OUTSZ*2
#define MAXROI 512
#define FGRID  2048
#define SBLK   256          // scatter blocks
#define SWARPS (SBLK * 8)   // scatter warp slots

__device__ float4 g_tab[MAXROI][4][2][GSAMP];  // {w0,w1,lo,hi}
__device__ unsigned g_work[MAXROI * CELLS];    // (r<<12)|(cell<<4)|m
__device__ int g_count;                         // starts 0, reset by scatter
__device__ int g_ticket;

__global__ __launch_bounds__(256)
void afp_fill_build(const float* __restrict__ rois, int R,
                    float4* __restrict__ out4, int nf4)
{
    __shared__ float s_w0[4][2][GSAMP];
    __shared__ float s_w1[4][2][GSAMP];

    const int tid = threadIdx.x;
    const int r   = blockIdx.x;

    if (r < R) {
        // Phase A: bilinear prep (reference fp32 op order, exactly).
        if (tid < 4 * 2 * GSAMP) {
            int l   = tid / (2 * GSAMP);
            int rem = tid - l * (2 * GSAMP);
            int a   = rem / GSAMP;       // 0=y, 1=x
            int j   = rem - a * GSAMP;

            float p1 = rois[r * 4 + (a == 0 ? 1 : 0)];
            float p2 = rois[r * 4 + (a == 0 ? 3 : 2)];
            #pragma unroll
            for (int i = 3; i >= 0; --i) {
                if (i >= l) {
                    float s = (float)(28 << i);
                    p1 = __fmul_rn(p1, s);
                    p2 = __fmul_rn(p2, s);
                }
            }
            float len  = fmaxf(__fadd_rn(p2, -p1), 1.0f);
            float t    = __fdiv_rn(len, 14.0f);
            float step = ((float)j + 0.5f) * 0.5f;
            float c    = __fadd_rn(p1, __fmul_rn(step, t));

            int L = 224 >> l;
            bool valid = (c >= -1.0f) && (c <= (float)L);
            c = fminf(fmaxf(c, 0.0f), (float)(L - 1));
            float lo   = floorf(c);
            float frac = __fadd_rn(c, -lo);
            int loi = (int)lo;
            int hii = loi + 1;
            if (loi >= L - 1) { loi = L - 1; hii = L - 1; frac = 0.0f; }
            float v  = valid ? 1.0f : 0.0f;
            float w0 = (1.0f - frac) * v;
            float w1 = frac * v;
            s_w0[l][a][j] = w0;
            s_w1[l][a][j] = w1;
            g_tab[r][l][a][j] = make_float4(w0, w1, __int_as_float(loi), __int_as_float(hii));
        }
        __syncthreads();

        // Phase B: compacted (roi, cell, mask) worklist.
        if (tid < CELLS) {
            int py = tid / OUTSZ;
            int px = tid - py * OUTSZ;
            unsigned m = 0;
            #pragma unroll
            for (int l = 0; l < 4; ++l) {
                float wy = s_w0[l][0][2*py]   + s_w1[l][0][2*py]
                         + s_w0[l][0][2*py+1] + s_w1[l][0][2*py+1];
                float wx = s_w0[l][1][2*px]   + s_w1[l][1][2*px]
                         + s_w0[l][1][2*px+1] + s_w1[l][1][2*px+1];
                if (wy > 0.0f && wx > 0.0f) m |= (1u << l);
            }
            if (m) {
                int pos = atomicAdd(&g_count, 1);
                g_work[pos] = ((unsigned)r << 12) | ((unsigned)tid << 4) | m;
            }
        }
    }

    // Coalesced zero-fill of the whole output (all 2048 blocks).
    const float4 z = make_float4(0.f, 0.f, 0.f, 0.f);
    for (int i = blockIdx.x * 256 + tid; i < nf4; i += FGRID * 256)
        out4[i] = z;
}

__global__ __launch_bounds__(256)
void afp_scatter(const float* __restrict__ f0, const float* __restrict__ f1,
                 const float* __restrict__ f2, const float* __restrict__ f3,
                 float* __restrict__ out)
{
    const int n    = g_count;            // visible via kernel-boundary ordering
    const int tid  = threadIdx.x;
    const int lane = tid & 31;
    const int gw   = blockIdx.x * 8 + (tid >> 5);  // global warp id
    const int xi   = lane & 3;           // x-tap index
    const int c8   = lane >> 2;          // channel sub-index 0..7
    const float* fl[4] = { f0, f1, f2, f3 };

    for (int e = gw; e < n; e += SWARPS) {
        const unsigned w = g_work[e];

        int r    = (int)(w >> 12);
        int cell = (int)((w >> 4) & 0xFF);
        unsigned m = w & 0xF;
        int py = cell / OUTSZ;
        int px = cell - py * OUTSZ;
        int sy = 2 * py, sx = 2 * px;

        float* obase = out + (size_t)r * (CH * CELLS) + cell;

        #pragma unroll 2
        for (int b = 0; b < 8; ++b) {     // 8 rounds x 32 channels
            const int cb = c8 + 32 * b;   // channels cb, cb+8, cb+16, cb+24
            float best[4] = {0.f, 0.f, 0.f, 0.f};

            #pragma unroll
            for (int l = 0; l < 4; ++l) {
                if (m & (1u << l)) {
                    const int W = 224 >> l;
                    float4 ty0 = g_tab[r][l][0][sy];
                    float4 ty1 = g_tab[r][l][0][sy + 1];
                    float4 tx0 = g_tab[r][l][1][sx];
                    float4 tx1 = g_tab[r][l][1][sx + 1];

                    float wx; int x;
                    if (xi == 0)      { wx = tx0.x; x = __float_as_int(tx0.z); }
                    else if (xi == 1) { wx = tx0.y; x = __float_as_int(tx0.w); }
                    else if (xi == 2) { wx = tx1.x; x = __float_as_int(tx1.z); }
                    else              { wx = tx1.y; x = __float_as_int(tx1.w); }

                    int y0 = __float_as_int(ty0.z) * W;
                    int y1 = __float_as_int(ty0.w) * W;
                    int y2 = __float_as_int(ty1.z) * W;
                    int y3 = __float_as_int(ty1.w) * W;

                    // 16 independent LDGs, front-batched.
                    float v[4][4];
                    #pragma unroll
                    for (int u = 0; u < 4; ++u) {
                        const float* fc = fl[l] + (size_t)(cb + 8 * u) * (W * W);
                        v[u][0] = fc[y0 + x];
                        v[u][1] = fc[y1 + x];
                        v[u][2] = fc[y2 + x];
                        v[u][3] = fc[y3 + x];
                    }
                    #pragma unroll
                    for (int u = 0; u < 4; ++u) {
                        float s = wx * (ty0.x * v[u][0] + ty0.y * v[u][1]
                                      + ty1.x * v[u][2] + ty1.y * v[u][3]);
                        s += __shfl_xor_sync(0xFFFFFFFFu, s, 1);
                        s += __shfl_xor_sync(0xFFFFFFFFu, s, 2);
                        best[u] = fmaxf(best[u], s * 0.25f);
                    }
                }
            }
            if (xi == 0) {
                #pragma unroll
                for (int u = 0; u < 4; ++u)
                    obase[(size_t)(cb + 8 * u) * CELLS] = best[u];
            }
        }
    }

    // Self-reset for the next graph replay: last block zeroes the counter.
    __syncthreads();
    if (tid == 0) {
        int t = atomicAdd(&g_ticket, 1);
        if (t == SBLK - 1) {
            g_count  = 0;
            g_ticket = 0;
        }
    }
}

extern "C" void kernel_launch(void* const* d_in, const int* in_sizes, int n_in,
                              void* d_out, int out_size)
{
    const float* f0   = (const float*)d_in[0];
    const float* f1   = (const float*)d_in[1];
    const float* f2   = (const float*)d_in[2];
    const float* f3   = (const float*)d_in[3];
    const float* rois = (const float*)d_in[4];
    int R = in_sizes[4] / 4;

    afp_fill_build<<<FGRID, 256>>>(rois, R, (float4*)d_out, out_size / 4);
    afp_scatter<<<SBLK, 256>>>(f0, f1, f2, f3, (float*)d_out);
}

// round 17
// speedup vs baseline: 1.3119x; 1.2323x over previous
#include <cuda_runtime.h>

// AdaptiveFeaturePooling: 4-level ROIAlign (out=14, sr=2) + max over levels.
// 2 graph nodes:
//  1) build <<<R,256>>>: bilinear tables, compacted worklist, dense per-ROI
//     validity mask (49 packed words per ROI).
//  2) fill+scatter <<<4R,256>>>: each block
//     a) processes <=1 worklist entry: 8 warps each take one 32-channel
//        round -> the whole entry is ONE batched gather round deep;
//     b) zero-fills a contiguous quarter-slice (64 channels of one ROI),
//        skipping valid cells via the smem-cached mask (no write race).
// g_count self-resets in node 2 via exit ticket (graph-replay safe).

#define OUTSZ  14
#define CELLS  196
#define CH     256
#define GSAMP  28           // OUTSZ*2
#define MAXROI 512
#define NGRP   49           // float4 groups per channel (196/4)
#define QF4    (64 * NGRP)  // float4 per quarter slice = 3136
#define SLICE4 (CH * NGRP)  // float4 per ROI slice = 12544

__device__ float4 g_tab[MAXROI][4][2][GSAMP];  // {w0,w1,lo,hi}
__device__ unsigned g_work[MAXROI * CELLS];    // (r<<12)|(cell<<4)|m
__device__ unsigned g_maskw[MAXROI * NGRP];    // packed 4 mask bytes per word
__device__ int g_count;                         // starts 0, reset by node 2
__device__ int g_ticket;

__global__ __launch_bounds__(256)
void afp_build(const float* __restrict__ rois)
{
    __shared__ float s_w0[4][2][GSAMP];
    __shared__ float s_w1[4][2][GSAMP];
    __shared__ unsigned char s_m[CELLS];

    const int tid = threadIdx.x;
    const int r   = blockIdx.x;

    // Phase A: bilinear prep (reference fp32 op order, exactly).
    if (tid < 4 * 2 * GSAMP) {
        int l   = tid / (2 * GSAMP);
        int rem = tid - l * (2 * GSAMP);
        int a   = rem / GSAMP;           // 0=y, 1=x
        int j   = rem - a * GSAMP;

        float p1 = rois[r * 4 + (a == 0 ? 1 : 0)];
        float p2 = rois[r * 4 + (a == 0 ? 3 : 2)];
        #pragma unroll
        for (int i = 3; i >= 0; --i) {
            if (i >= l) {
                float s = (float)(28 << i);
                p1 = __fmul_rn(p1, s);
                p2 = __fmul_rn(p2, s);
            }
        }
        float len  = fmaxf(__fadd_rn(p2, -p1), 1.0f);
        float t    = __fdiv_rn(len, 14.0f);
        float step = ((float)j + 0.5f) * 0.5f;
        float c    = __fadd_rn(p1, __fmul_rn(step, t));

        int L = 224 >> l;
        bool valid = (c >= -1.0f) && (c <= (float)L);
        c = fminf(fmaxf(c, 0.0f), (float)(L - 1));
        float lo   = floorf(c);
        float frac = __fadd_rn(c, -lo);
        int loi = (int)lo;
        int hii = loi + 1;
        if (loi >= L - 1) { loi = L - 1; hii = L - 1; frac = 0.0f; }
        float v  = valid ? 1.0f : 0.0f;
        float w0 = (1.0f - frac) * v;
        float w1 = frac * v;
        s_w0[l][a][j] = w0;
        s_w1[l][a][j] = w1;
        g_tab[r][l][a][j] = make_float4(w0, w1, __int_as_float(loi), __int_as_float(hii));
    }
    __syncthreads();

    // Phase B: per-cell mask + compacted worklist.
    if (tid < CELLS) {
        int py = tid / OUTSZ;
        int px = tid - py * OUTSZ;
        unsigned m = 0;
        #pragma unroll
        for (int l = 0; l < 4; ++l) {
            float wy = s_w0[l][0][2*py]   + s_w1[l][0][2*py]
                     + s_w0[l][0][2*py+1] + s_w1[l][0][2*py+1];
            float wx = s_w0[l][1][2*px]   + s_w1[l][1][2*px]
                     + s_w0[l][1][2*px+1] + s_w1[l][1][2*px+1];
            if (wy > 0.0f && wx > 0.0f) m |= (1u << l);
        }
        s_m[tid] = (unsigned char)m;
        if (m) {
            int pos = atomicAdd(&g_count, 1);
            g_work[pos] = ((unsigned)r << 12) | ((unsigned)tid << 4) | m;
        }
    }
    __syncthreads();

    // Packed 4-cell mask words for the fill's skip test.
    if (tid < NGRP) {
        int k = tid * 4;
        unsigned w = (unsigned)s_m[k]
                   | ((unsigned)s_m[k+1] << 8)
                   | ((unsigned)s_m[k+2] << 16)
                   | ((unsigned)s_m[k+3] << 24);
        g_maskw[r * NGRP + tid] = w;
    }
}

__global__ __launch_bounds__(256)
void afp_fill_scatter(const float* __restrict__ f0, const float* __restrict__ f1,
                      const float* __restrict__ f2, const float* __restrict__ f3,
                      float* __restrict__ out, int R)
{
    __shared__ unsigned s_mk[NGRP];

    const int tid  = threadIdx.x;
    const int bid  = blockIdx.x;
    const int grid = gridDim.x;          // 4R
    const int n    = g_count;            // ordered by kernel boundary

    // ---- (a) scatter: <=1 worklist entry per block, 8 warps = 8 rounds ----
    {
        const int lane = tid & 31;
        const int wid  = tid >> 5;       // warp id = channel round
        const int xi   = lane & 3;       // x-tap index
        const int c8   = lane >> 2;      // channel sub-index 0..7
        const float* fl[4] = { f0, f1, f2, f3 };

        for (int e = bid; e < n; e += grid) {
            const unsigned w = g_work[e];
            int r    = (int)(w >> 12);
            int cell = (int)((w >> 4) & 0xFF);
            unsigned m = w & 0xF;
            int py = cell / OUTSZ;
            int px = cell - py * OUTSZ;
            int sy = 2 * py, sx = 2 * px;

            float* obase = out + (size_t)r * (CH * CELLS) + cell;
            const int cb = c8 + 32 * wid;         // this warp's 32 channels
            float best[4] = {0.f, 0.f, 0.f, 0.f};

            #pragma unroll
            for (int l = 0; l < 4; ++l) {
                if (m & (1u << l)) {
                    const int W = 224 >> l;
                    float4 ty0 = g_tab[r][l][0][sy];
                    float4 ty1 = g_tab[r][l][0][sy + 1];
                    float4 tx0 = g_tab[r][l][1][sx];
                    float4 tx1 = g_tab[r][l][1][sx + 1];

                    float wx; int x;
                    if (xi == 0)      { wx = tx0.x; x = __float_as_int(tx0.z); }
                    else if (xi == 1) { wx = tx0.y; x = __float_as_int(tx0.w); }
                    else if (xi == 2) { wx = tx1.x; x = __float_as_int(tx1.z); }
                    else              { wx = tx1.y; x = __float_as_int(tx1.w); }

                    int y0 = __float_as_int(ty0.z) * W;
                    int y1 = __float_as_int(ty0.w) * W;
                    int y2 = __float_as_int(ty1.z) * W;
                    int y3 = __float_as_int(ty1.w) * W;

                    // 16 independent LDGs, front-batched (one latency round).
                    float v[4][4];
                    #pragma unroll
                    for (int u = 0; u < 4; ++u) {
                        const float* fc = fl[l] + (size_t)(cb + 8 * u) * (W * W);
                        v[u][0] = fc[y0 + x];
                        v[u][1] = fc[y1 + x];
                        v[u][2] = fc[y2 + x];
                        v[u][3] = fc[y3 + x];
                    }
                    #pragma unroll
                    for (int u = 0; u < 4; ++u) {
                        float s = wx * (ty0.x * v[u][0] + ty0.y * v[u][1]
                                      + ty1.x * v[u][2] + ty1.y * v[u][3]);
                        s += __shfl_xor_sync(0xFFFFFFFFu, s, 1);
                        s += __shfl_xor_sync(0xFFFFFFFFu, s, 2);
                        best[u] = fmaxf(best[u], s * 0.25f);
                    }
                }
            }
            if (xi == 0) {
                #pragma unroll
                for (int u = 0; u < 4; ++u)
                    obase[(size_t)(cb + 8 * u) * CELLS] = best[u];
            }
        }
    }

    // ---- (b) fill: contiguous quarter-slice, skipping valid cells ----
    {
        const int r = bid >> 2;          // ROI
        const int q = bid & 3;           // quarter (64 channels)
        if (r < R) {
            if (tid < NGRP) s_mk[tid] = g_maskw[r * NGRP + tid];
            __syncthreads();

            float4* o4 = reinterpret_cast<float4*>(out) + (size_t)r * SLICE4 + q * QF4;
            const float4 z4 = make_float4(0.f, 0.f, 0.f, 0.f);
            int k = tid % NGRP;          // group index within channel
            #pragma unroll 4
            for (int i = tid; i < QF4; i += 256) {
                unsigned mw = s_mk[k];
                if (mw == 0u) {
                    o4[i] = z4;
                } else {
                    float* p = reinterpret_cast<float*>(o4 + i);
                    if (!(mw & 0x000000FFu)) p[0] = 0.0f;
                    if (!(mw & 0x0000FF00u)) p[1] = 0.0f;
                    if (!(mw & 0x00FF0000u)) p[2] = 0.0f;
                    if (!(mw & 0xFF000000u)) p[3] = 0.0f;
                }
                k += 256 % NGRP;         // 256 = 5*49 + 11
                if (k >= NGRP) k -= NGRP;
            }
        }
    }

    // Self-reset for the next graph replay: last block zeroes the counter.
    __syncthreads();
    if (tid == 0) {
        int t = atomicAdd(&g_ticket, 1);
        if (t == grid - 1) {
            g_count  = 0;
            g_ticket = 0;
        }
    }
}

extern "C" void kernel_launch(void* const* d_in, const int* in_sizes, int n_in,
                              void* d_out, int out_size)
{
    const float* f0   = (const float*)d_in[0];
    const float* f1   = (const float*)d_in[1];
    const float* f2   = (const float*)d_in[2];
    const float* f3   = (const float*)d_in[3];
    const float* rois = (const float*)d_in[4];
    int R = in_sizes[4] / 4;

    afp_build<<<R, 256>>>(rois);
    afp_fill_scatter<<<4 * R, 256>>>(f0, f1, f2, f3, (float*)d_out, R);
}